// round 10
// baseline (speedup 1.0000x reference)
#include <cuda_runtime.h>
#include <cstdint>

#define BB 8
#define SS 1024
#define DD 1024
#define HH 16
#define DHH 64
#define QKVN 3072
#define MROWS 8192
#define KDIM 1024

// ---------------- scratch ----------------------------------------------------
__device__ float g_w[KDIM * QKVN];                 // packed QKV weights (tf32-rounded)
__device__ float g_b[QKVN];
__device__ float g_qkv[(size_t)MROWS * QKVN];      // tf32-rounded (GEMM epilogue)
__device__ float g_ctx[(size_t)MROWS * DD];        // tf32-rounded (attn epilogue)
__device__ float g_xt[(size_t)MROWS * KDIM];       // tf32-rounded inputs
__device__ float g_wo[KDIM * DD];                  // tf32-rounded Wo

// ---------------- tf32 helpers ----------------------------------------------
__device__ __forceinline__ unsigned f2tf32(float x) {
    unsigned u;
    asm("cvt.rna.tf32.f32 %0, %1;" : "=r"(u) : "f"(x));
    return u;
}

#define MMA_TF32(c, a, b)                                                     \
    asm volatile("mma.sync.aligned.m16n8k8.row.col.f32.tf32.tf32.f32 "        \
                 "{%0,%1,%2,%3}, {%4,%5,%6,%7}, {%8,%9}, {%0,%1,%2,%3};"      \
                 : "+f"((c)[0]), "+f"((c)[1]), "+f"((c)[2]), "+f"((c)[3])     \
                 : "r"((a).x), "r"((a).y), "r"((a).z), "r"((a).w),            \
                   "r"((b).x), "r"((b).y))

#define CPA16(dst, src)                                                       \
    asm volatile("cp.async.cg.shared.global [%0], [%1], 16;"                  \
                 :: "r"(dst), "l"(__cvta_generic_to_global(src)))
#define CP_COMMIT() asm volatile("cp.async.commit_group;")

// ---------------- pack Wq/Wk/Wv [H,D,DH] -> g_w [D][3*H*DH] (tf32) -----------
__global__ void pack_w_kernel(const float* __restrict__ Wq, const float* __restrict__ bq,
                              const float* __restrict__ Wk, const float* __restrict__ bk,
                              const float* __restrict__ Wv, const float* __restrict__ bv)
{
    int idx = blockIdx.x * 256 + threadIdx.x;
    if (idx < KDIM * QKVN) {
        int d   = idx / QKVN;
        int col = idx - d * QKVN;
        int which = col >> 10;
        int he  = col & 1023;
        int h   = he >> 6;
        int e   = he & 63;
        const float* W = (which == 0) ? Wq : ((which == 1) ? Wk : Wv);
        g_w[idx] = __uint_as_float(f2tf32(W[(h * KDIM + d) * DHH + e]));
    }
    if (idx < QKVN) {
        int which = idx >> 10;
        int he = idx & 1023;
        const float* bb = (which == 0) ? bq : ((which == 1) ? bk : bv);
        g_b[idx] = bb[he];
    }
}

// ---------------- elementwise tf32 rounding ----------------------------------
__global__ void round_tf32_kernel(const float4* __restrict__ in, float4* __restrict__ out, int n4)
{
    int i = blockIdx.x * 256 + threadIdx.x;
    if (i < n4) {
        float4 v = in[i];
        v.x = __uint_as_float(f2tf32(v.x));
        v.y = __uint_as_float(f2tf32(v.y));
        v.z = __uint_as_float(f2tf32(v.z));
        v.w = __uint_as_float(f2tf32(v.w));
        out[i] = v;
    }
}

// ---------------- tf32 GEMM v5: BK=32, 3-stage cp.async, 128x256 -------------
// Stage = A[2 halves][128][16] + B[2 halves][16][256] = 12288 words (48KB).
// Each half uses the v4-verified swizzles.
__global__ __launch_bounds__(256, 1)
void tf32_gemm_bias(const float* __restrict__ A, const float* __restrict__ Bm,
                    const float* __restrict__ bias, float* __restrict__ C,
                    int M, int N, int K, int roundC)
{
    extern __shared__ unsigned S[];   // 3 * 12288 words = 144KB

    const int tid  = threadIdx.x;
    const int lane = tid & 31;
    const int wid  = tid >> 5;
    const int wm   = wid >> 2;
    const int wn   = wid & 3;
    const int bm   = blockIdx.y * 128;
    const int bn   = blockIdx.x * 256;
    const int g    = lane >> 2;
    const int t    = lane & 3;

    unsigned sbase;
    asm("{ .reg .u64 x0; cvta.to.shared.u64 x0, %1; cvt.u32.u64 %0, x0; }"
        : "=r"(sbase) : "l"(S));

    // ---- A cp.async: thread -> row arow (0..127), half ah, chunks 0..3
    const int arow = tid >> 1;
    const int ah   = tid & 1;
    const int swA  = (arow >> 1) & 3;
    const float* Asrc = A + (size_t)(bm + arow) * K + ah * 16;
    unsigned adst[4];
#pragma unroll
    for (int i = 0; i < 4; i++)
        adst[i] = sbase + (unsigned)(ah * 2048 + arow * 16 + ((i ^ swA) & 3) * 4) * 4;

    // ---- B cp.async: thread -> local k row kbr in both halves, 4 col groups
    const int kbr = tid >> 4;
    const int bc  = tid & 15;
    const int sB  = (2 * kbr) & 7;
    const float* Bsrc = Bm + (size_t)kbr * N + bn + 4 * bc;
    unsigned bdst[4];
#pragma unroll
    for (int u = 0; u < 4; u++)
        bdst[u] = sbase + (unsigned)(4096 + kbr * 256 + (((bc + 16 * u) ^ sB) & 63) * 4) * 4;

#define GEMM_ISSUE(it, stg) do {                                               \
        unsigned off_ = (unsigned)(stg) * 49152u;                              \
        const float* as_ = Asrc + (size_t)(it) * 32;                           \
        CPA16(adst[0] + off_, as_);                                            \
        CPA16(adst[1] + off_, as_ + 4);                                        \
        CPA16(adst[2] + off_, as_ + 8);                                        \
        CPA16(adst[3] + off_, as_ + 12);                                       \
        const float* b0_ = Bsrc + (size_t)(it) * 32 * N;                       \
        const float* b1_ = b0_ + (size_t)16 * N;                               \
        CPA16(bdst[0] + off_, b0_);                                            \
        CPA16(bdst[1] + off_, b0_ + 64);                                       \
        CPA16(bdst[2] + off_, b0_ + 128);                                      \
        CPA16(bdst[3] + off_, b0_ + 192);                                      \
        CPA16(bdst[0] + off_ + 16384u, b1_);                                   \
        CPA16(bdst[1] + off_ + 16384u, b1_ + 64);                              \
        CPA16(bdst[2] + off_ + 16384u, b1_ + 128);                             \
        CPA16(bdst[3] + off_ + 16384u, b1_ + 192);                             \
    } while (0)

    float acc[4][8][4];
#pragma unroll
    for (int m = 0; m < 4; m++)
#pragma unroll
        for (int nf = 0; nf < 8; nf++)
#pragma unroll
            for (int e = 0; e < 4; e++) acc[m][nf][e] = 0.f;

    GEMM_ISSUE(0, 0); CP_COMMIT();
    GEMM_ISSUE(1, 1); CP_COMMIT();

    const int NIT = K >> 5;
    const int swa = (g >> 1) & 3;
    int cur = 0;

    for (int it = 0; it < NIT; ++it) {
        asm volatile("cp.async.wait_group 1;");
        __syncthreads();
        if (it + 2 < NIT) {
            int s2 = cur + 2; if (s2 >= 3) s2 -= 3;
            GEMM_ISSUE(it + 2, s2);
        }
        CP_COMMIT();

        const unsigned* Sa = S + cur * 12288;
        const unsigned* Sb = Sa + 4096;

#pragma unroll
        for (int sl = 0; sl < 4; ++sl) {
            const int half = sl >> 1, sll = sl & 1;
            const unsigned* Ha = Sa + half * 2048;
            const unsigned* Hb = Sb + half * 4096;
            uint4 af[4];
            const int cx = ((2 * sll) ^ swa) << 2;
            const int cz = ((2 * sll + 1) ^ swa) << 2;
#pragma unroll
            for (int m = 0; m < 4; m++) {
                int rb = (wm * 64 + m * 16 + g) * 16 + t;
                af[m].x = Ha[rb + cx];
                af[m].y = Ha[rb + 128 + cx];
                af[m].z = Ha[rb + cz];
                af[m].w = Ha[rb + 128 + cz];
            }
            uint2 bf[8];
            const int r0 = (sll * 8 + t) * 256 + (g & 3);
            const int r1 = r0 + 4 * 256;
#pragma unroll
            for (int nf = 0; nf < 8; nf++) {
                int c2 = ((wn * 16 + nf * 2 + (g >> 2)) ^ (2 * t)) & 63;
                bf[nf].x = Hb[r0 + c2 * 4];
                bf[nf].y = Hb[r1 + c2 * 4];
            }
#pragma unroll
            for (int m = 0; m < 4; m++)
#pragma unroll
                for (int nf = 0; nf < 8; nf++)
                    MMA_TF32(acc[m][nf], af[m], bf[nf]);
        }
        if (++cur == 3) cur = 0;
    }

    // ---- epilogue
#pragma unroll
    for (int m = 0; m < 4; m++) {
        int row = bm + wm * 64 + m * 16 + g;
#pragma unroll
        for (int nf = 0; nf < 8; nf++) {
            int col = bn + wn * 64 + nf * 8 + 2 * t;
            float b0 = bias[col], b1 = bias[col + 1];
            float2 v0 = make_float2(acc[m][nf][0] + b0, acc[m][nf][1] + b1);
            float2 v1 = make_float2(acc[m][nf][2] + b0, acc[m][nf][3] + b1);
            if (roundC) {
                v0.x = __uint_as_float(f2tf32(v0.x));
                v0.y = __uint_as_float(f2tf32(v0.y));
                v1.x = __uint_as_float(f2tf32(v1.x));
                v1.y = __uint_as_float(f2tf32(v1.y));
            }
            *(float2*)&C[(size_t)row * N + col]       = v0;
            *(float2*)&C[(size_t)(row + 8) * N + col] = v1;
        }
    }
#undef GEMM_ISSUE
}

// ---------------- attention v4: 128-key chunks, cp.async KV, Q in regs -------
// grid (S/128, B*H), 256 threads. Smem words:
//   pf [0,8192)                P frags (per warp 1024)
//   K  [8192,  8192+2*8704)    [128][68] double-buffered
//   V  [25600, 25600+2*8704)
__global__ __launch_bounds__(256)
void attn_mma_kernel(const int* __restrict__ mask)
{
    extern __shared__ unsigned sm_u[];
    unsigned* pf = sm_u;

    const int tid  = threadIdx.x;
    const int lane = tid & 31;
    const int wq   = tid >> 5;
    const int g    = lane >> 2;
    const int t    = lane & 3;
    const int b    = blockIdx.y >> 4;
    const int h    = blockIdx.y & 15;
    const int q0   = blockIdx.x * 128;

    unsigned sbase;
    asm("{ .reg .u64 x0; cvta.to.shared.u64 x0, %1; cvt.u32.u64 %0, x0; }"
        : "=r"(sbase) : "l"(sm_u));

    // ---- Q fragments in registers
    uint4 qreg[8];
    {
        const float* qb = g_qkv + ((size_t)(b * SS + q0 + wq * 16)) * QKVN + h * DHH;
#pragma unroll
        for (int sl = 0; sl < 8; sl++) {
            float x0 = qb[(size_t)g * QKVN + sl * 8 + t];
            float x1 = qb[(size_t)(g + 8) * QKVN + sl * 8 + t];
            float x2 = qb[(size_t)g * QKVN + sl * 8 + t + 4];
            float x3 = qb[(size_t)(g + 8) * QKVN + sl * 8 + t + 4];
            qreg[sl].x = __float_as_uint(x0 * 0.03125f);
            qreg[sl].y = __float_as_uint(x1 * 0.03125f);
            qreg[sl].z = __float_as_uint(x2 * 0.03125f);
            qreg[sl].w = __float_as_uint(x3 * 0.03125f);
        }
    }

    // ---- cp.async mapping: thread -> KV row (tid>>1), 32B half (tid&1)
    const int krow = tid >> 1;
    const int kqh  = (tid & 1) * 32;   // float offset within the 64-wide row
    const size_t srcrow = ((size_t)(b * SS) + krow) * QKVN + h * DHH + kqh;
    const unsigned kdst = sbase + (unsigned)(8192  + krow * 68 + kqh) * 4;
    const unsigned vdst = sbase + (unsigned)(25600 + krow * 68 + kqh) * 4;

#define AT_ISSUE(ch) do {                                                      \
        unsigned bo_ = ((ch) & 1) ? 34816u : 0u;                               \
        const float* kp_ = g_qkv + srcrow + (size_t)(ch) * 128 * QKVN + 1024;  \
        const float* vp_ = kp_ + 1024;                                         \
        CPA16(kdst + bo_,       kp_);                                          \
        CPA16(kdst + bo_ + 16,  kp_ + 4);                                      \
        CPA16(kdst + bo_ + 32,  kp_ + 8);                                      \
        CPA16(kdst + bo_ + 48,  kp_ + 12);                                     \
        CPA16(kdst + bo_ + 64,  kp_ + 16);                                     \
        CPA16(kdst + bo_ + 80,  kp_ + 20);                                     \
        CPA16(kdst + bo_ + 96,  kp_ + 24);                                     \
        CPA16(kdst + bo_ + 112, kp_ + 28);                                     \
        CPA16(vdst + bo_,       vp_);                                          \
        CPA16(vdst + bo_ + 16,  vp_ + 4);                                      \
        CPA16(vdst + bo_ + 32,  vp_ + 8);                                      \
        CPA16(vdst + bo_ + 48,  vp_ + 12);                                     \
        CPA16(vdst + bo_ + 64,  vp_ + 16);                                     \
        CPA16(vdst + bo_ + 80,  vp_ + 20);                                     \
        CPA16(vdst + bo_ + 96,  vp_ + 24);                                     \
        CPA16(vdst + bo_ + 112, vp_ + 28);                                     \
        CP_COMMIT();                                                           \
    } while (0)

    float o[8][4];
#pragma unroll
    for (int nf = 0; nf < 8; nf++)
#pragma unroll
        for (int e = 0; e < 4; e++) o[nf][e] = 0.f;
    float m0 = -1e30f, m1 = -1e30f, l0 = 0.f, l1 = 0.f;

    const size_t mbase = (size_t)b * SS * SS;
    unsigned* pw = pf + wq * 1024;

    AT_ISSUE(0);

#pragma unroll 1
    for (int ch = 0; ch < 8; ++ch) {
        if (ch + 1 < 8) {
            AT_ISSUE(ch + 1);
            asm volatile("cp.async.wait_group 1;");
        } else {
            asm volatile("cp.async.wait_group 0;");
        }
        __syncthreads();

        const unsigned* KS = sm_u + 8192  + ((ch & 1) ? 8704 : 0);
        const unsigned* VS = sm_u + 25600 + ((ch & 1) ? 8704 : 0);

        // ---- GEMM1: S[16 q][128 keys]
        float s[16][4];
#pragma unroll
        for (int nf = 0; nf < 16; nf++)
#pragma unroll
            for (int e = 0; e < 4; e++) s[nf][e] = 0.f;
#pragma unroll
        for (int sl = 0; sl < 8; ++sl) {
            const int ab = g * 68 + sl * 8 + t;
#pragma unroll
            for (int nf = 0; nf < 16; nf++) {
                uint2 bb;
                bb.x = KS[nf * 544 + ab];
                bb.y = KS[nf * 544 + ab + 4];
                MMA_TF32(s[nf], qreg[sl], bb);
            }
        }

        // ---- mask (nonzero -> -1e9)
        const int rg = q0 + wq * 16 + g;
        const int kb = ch * 128;
#pragma unroll
        for (int nf = 0; nf < 16; nf++) {
            int col = kb + nf * 8 + 2 * t;
            int2 mk0 = *(const int2*)(mask + mbase + (size_t)rg * SS + col);
            int2 mk1 = *(const int2*)(mask + mbase + (size_t)(rg + 8) * SS + col);
            if (mk0.x) s[nf][0] = -1e9f;
            if (mk0.y) s[nf][1] = -1e9f;
            if (mk1.x) s[nf][2] = -1e9f;
            if (mk1.y) s[nf][3] = -1e9f;
        }

        // ---- online softmax
        float mx0 = -1e30f, mx1 = -1e30f;
#pragma unroll
        for (int nf = 0; nf < 16; nf++) {
            mx0 = fmaxf(mx0, fmaxf(s[nf][0], s[nf][1]));
            mx1 = fmaxf(mx1, fmaxf(s[nf][2], s[nf][3]));
        }
        mx0 = fmaxf(mx0, __shfl_xor_sync(0xffffffffu, mx0, 1));
        mx0 = fmaxf(mx0, __shfl_xor_sync(0xffffffffu, mx0, 2));
        mx1 = fmaxf(mx1, __shfl_xor_sync(0xffffffffu, mx1, 1));
        mx1 = fmaxf(mx1, __shfl_xor_sync(0xffffffffu, mx1, 2));
        float mn0 = fmaxf(m0, mx0), mn1 = fmaxf(m1, mx1);
        float a0 = __expf(m0 - mn0), a1 = __expf(m1 - mn1);
        m0 = mn0; m1 = mn1;

        float ps0 = 0.f, ps1 = 0.f;
#pragma unroll
        for (int nf = 0; nf < 16; nf++) {
            s[nf][0] = __expf(s[nf][0] - mn0);
            s[nf][1] = __expf(s[nf][1] - mn0);
            s[nf][2] = __expf(s[nf][2] - mn1);
            s[nf][3] = __expf(s[nf][3] - mn1);
            ps0 += s[nf][0] + s[nf][1];
            ps1 += s[nf][2] + s[nf][3];
        }
        ps0 += __shfl_xor_sync(0xffffffffu, ps0, 1);
        ps0 += __shfl_xor_sync(0xffffffffu, ps0, 2);
        ps1 += __shfl_xor_sync(0xffffffffu, ps1, 1);
        ps1 += __shfl_xor_sync(0xffffffffu, ps1, 2);
        l0 = l0 * a0 + ps0;
        l1 = l1 * a1 + ps1;
#pragma unroll
        for (int nf = 0; nf < 8; nf++) {
            o[nf][0] *= a0; o[nf][1] *= a0;
            o[nf][2] *= a1; o[nf][3] *= a1;
        }

        // ---- GEMM2 in two passes of 8 key-slabs, reusing the per-warp P buf
        const int ln0 = (g << 2) | ((2 * t) & 3);
        const int ln1 = (g << 2) | ((2 * t + 1) & 3);
        const int sl0 = (t >> 1) << 1;
#pragma unroll
        for (int pp = 0; pp < 2; ++pp) {
#pragma unroll
            for (int nf2 = 0; nf2 < 8; nf2++) {
                const float* pv = s[pp * 8 + nf2];
                uint2 w0 = make_uint2(f2tf32(pv[0]), f2tf32(pv[2]));
                uint2 w1 = make_uint2(f2tf32(pv[1]), f2tf32(pv[3]));
                *(uint2*)&pw[nf2 * 128 + ln0 * 4 + sl0] = w0;
                *(uint2*)&pw[nf2 * 128 + ln1 * 4 + sl0] = w1;
            }
            __syncwarp();
#pragma unroll
            for (int sl2 = 0; sl2 < 8; ++sl2) {
                uint4 a = *(const uint4*)&pw[sl2 * 128 + lane * 4];
                const int vb = ((pp * 8 + sl2) * 8 + t) * 68 + g;
#pragma unroll
                for (int nf = 0; nf < 8; nf++) {
                    uint2 bb;
                    bb.x = VS[vb + nf * 8];
                    bb.y = VS[vb + nf * 8 + 4 * 68];
                    MMA_TF32(o[nf], a, bb);
                }
            }
            __syncwarp();
        }
        __syncthreads();   // KV buffers safe to overwrite next chunk
    }

    // ---- epilogue (tf32-rounded for the out-proj GEMM)
    float i0 = 1.f / l0, i1 = 1.f / l1;
    int row0 = q0 + wq * 16 + g;
#pragma unroll
    for (int nf = 0; nf < 8; nf++) {
        int col = h * DHH + nf * 8 + 2 * t;
        float2 v0 = make_float2(__uint_as_float(f2tf32(o[nf][0] * i0)),
                                __uint_as_float(f2tf32(o[nf][1] * i0)));
        float2 v1 = make_float2(__uint_as_float(f2tf32(o[nf][2] * i1)),
                                __uint_as_float(f2tf32(o[nf][3] * i1)));
        *(float2*)(g_ctx + (size_t)(b * SS + row0) * DD + col)     = v0;
        *(float2*)(g_ctx + (size_t)(b * SS + row0 + 8) * DD + col) = v1;
    }
#undef AT_ISSUE
}

// ---------------- launch -----------------------------------------------------
extern "C" void kernel_launch(void* const* d_in, const int* in_sizes, int n_in,
                              void* d_out, int out_size)
{
    const float* x  = (const float*)d_in[0];
    const int* mask = (const int*)d_in[1];
    const float* Wq = (const float*)d_in[2];
    const float* bq = (const float*)d_in[3];
    const float* Wk = (const float*)d_in[4];
    const float* bk = (const float*)d_in[5];
    const float* Wv = (const float*)d_in[6];
    const float* bv = (const float*)d_in[7];
    const float* Wo = (const float*)d_in[8];
    const float* bo = (const float*)d_in[9];
    float* out = (float*)d_out;

    void *p_w, *p_b, *p_qkv, *p_ctx, *p_xt, *p_wo;
    cudaGetSymbolAddress(&p_w, g_w);
    cudaGetSymbolAddress(&p_b, g_b);
    cudaGetSymbolAddress(&p_qkv, g_qkv);
    cudaGetSymbolAddress(&p_ctx, g_ctx);
    cudaGetSymbolAddress(&p_xt, g_xt);
    cudaGetSymbolAddress(&p_wo, g_wo);

    const int ATTN_SMEM = 43008 * (int)sizeof(unsigned);      // 172KB
    const int GEMM_SMEM = 3 * 12288 * (int)sizeof(unsigned);  // 144KB
    static int smem_set = 0;
    if (!smem_set) {
        cudaFuncSetAttribute(attn_mma_kernel, cudaFuncAttributeMaxDynamicSharedMemorySize, ATTN_SMEM);
        cudaFuncSetAttribute(tf32_gemm_bias, cudaFuncAttributeMaxDynamicSharedMemorySize, GEMM_SMEM);
        smem_set = 1;
    }

    round_tf32_kernel<<<(MROWS * KDIM / 4 + 255) / 256, 256>>>(
        (const float4*)x, (float4*)p_xt, MROWS * KDIM / 4);
    round_tf32_kernel<<<(KDIM * DD / 4 + 255) / 256, 256>>>(
        (const float4*)Wo, (float4*)p_wo, KDIM * DD / 4);
    pack_w_kernel<<<(KDIM * QKVN + 255) / 256, 256>>>(Wq, bq, Wk, bk, Wv, bv);

    // QKV projection -> tf32-rounded
    tf32_gemm_bias<<<dim3(QKVN / 256, MROWS / 128), 256, GEMM_SMEM>>>(
        (const float*)p_xt, (const float*)p_w, (const float*)p_b, (float*)p_qkv,
        MROWS, QKVN, KDIM, 1);

    // fused masked attention
    attn_mma_kernel<<<dim3(SS / 128, BB * HH), 256, ATTN_SMEM>>>(mask);

    // output projection -> fp32 output
    tf32_gemm_bias<<<dim3(DD / 256, MROWS / 128), 256, GEMM_SMEM>>>(
        (const float*)p_ctx, (const float*)p_wo, bo, out, MROWS, DD, KDIM, 0);
}

// round 11
// speedup vs baseline: 1.1327x; 1.1327x over previous
#include <cuda_runtime.h>
#include <cstdint>

#define BB 8
#define SS 1024
#define DD 1024
#define HH 16
#define DHH 64
#define QKVN 3072
#define MROWS 8192
#define KDIM 1024

// ---------------- scratch ----------------------------------------------------
__device__ float g_w[KDIM * QKVN];                 // packed QKV weights (tf32-rounded)
__device__ float g_b[QKVN];
__device__ float g_qkv[(size_t)MROWS * QKVN];      // tf32-rounded (GEMM epilogue)
__device__ float g_ctx[(size_t)MROWS * DD];        // tf32-rounded (attn epilogue)
__device__ float g_xt[(size_t)MROWS * KDIM];       // tf32-rounded inputs
__device__ float g_wo[KDIM * DD];                  // tf32-rounded Wo

// ---------------- tf32 helpers ----------------------------------------------
__device__ __forceinline__ unsigned f2tf32(float x) {
    unsigned u;
    asm("cvt.rna.tf32.f32 %0, %1;" : "=r"(u) : "f"(x));
    return u;
}

#define MMA_TF32(c, a, b)                                                     \
    asm volatile("mma.sync.aligned.m16n8k8.row.col.f32.tf32.tf32.f32 "        \
                 "{%0,%1,%2,%3}, {%4,%5,%6,%7}, {%8,%9}, {%0,%1,%2,%3};"      \
                 : "+f"((c)[0]), "+f"((c)[1]), "+f"((c)[2]), "+f"((c)[3])     \
                 : "r"((a).x), "r"((a).y), "r"((a).z), "r"((a).w),            \
                   "r"((b).x), "r"((b).y))

#define CPA16(dst, src)                                                       \
    asm volatile("cp.async.cg.shared.global [%0], [%1], 16;"                  \
                 :: "r"(dst), "l"(__cvta_generic_to_global(src)))
#define CP_COMMIT() asm volatile("cp.async.commit_group;")

// ---------------- pack Wq/Wk/Wv [H,D,DH] -> g_w [D][3*H*DH] (tf32) -----------
__global__ void pack_w_kernel(const float* __restrict__ Wq, const float* __restrict__ bq,
                              const float* __restrict__ Wk, const float* __restrict__ bk,
                              const float* __restrict__ Wv, const float* __restrict__ bv)
{
    int idx = blockIdx.x * 256 + threadIdx.x;
    if (idx < KDIM * QKVN) {
        int d   = idx / QKVN;
        int col = idx - d * QKVN;
        int which = col >> 10;
        int he  = col & 1023;
        int h   = he >> 6;
        int e   = he & 63;
        const float* W = (which == 0) ? Wq : ((which == 1) ? Wk : Wv);
        g_w[idx] = __uint_as_float(f2tf32(W[(h * KDIM + d) * DHH + e]));
    }
    if (idx < QKVN) {
        int which = idx >> 10;
        int he = idx & 1023;
        const float* bb = (which == 0) ? bq : ((which == 1) ? bk : bv);
        g_b[idx] = bb[he];
    }
}

// ---------------- elementwise tf32 rounding ----------------------------------
__global__ void round_tf32_kernel(const float4* __restrict__ in, float4* __restrict__ out, int n4)
{
    int i = blockIdx.x * 256 + threadIdx.x;
    if (i < n4) {
        float4 v = in[i];
        v.x = __uint_as_float(f2tf32(v.x));
        v.y = __uint_as_float(f2tf32(v.y));
        v.z = __uint_as_float(f2tf32(v.z));
        v.w = __uint_as_float(f2tf32(v.w));
        out[i] = v;
    }
}

// ---------------- tf32 GEMM v6: 512 threads (16 warps), BK=16, 4-stage -------
// Same 128x256 block tile & verified swizzles as v4; warp tile 64x32.
// 4 warps/SMSP for latency hiding; acc 64 regs/thread.
__global__ __launch_bounds__(512, 1)
void tf32_gemm_bias(const float* __restrict__ A, const float* __restrict__ Bm,
                    const float* __restrict__ bias, float* __restrict__ C,
                    int M, int N, int K, int roundC)
{
    extern __shared__ unsigned S[];   // 4 * 6144 words = 96KB

    const int tid  = threadIdx.x;
    const int lane = tid & 31;
    const int wid  = tid >> 5;          // 0..15
    const int wm   = wid >> 3;          // 0..1
    const int wn   = wid & 7;           // 0..7
    const int bm   = blockIdx.y * 128;
    const int bn   = blockIdx.x * 256;
    const int g    = lane >> 2;
    const int t    = lane & 3;

    unsigned sbase;
    asm("{ .reg .u64 x0; cvta.to.shared.u64 x0, %1; cvt.u32.u64 %0, x0; }"
        : "=r"(sbase) : "l"(S));

    // ---- A cp.async: thread -> row arow (0..127), k-chunk ac (0..3)
    const int arow = tid >> 2;
    const int ac   = tid & 3;
    const int swA  = (arow >> 1) & 3;
    const float* Asrc = A + (size_t)(bm + arow) * K + 4 * ac;
    const unsigned adst = sbase + (unsigned)(arow * 16 + ((ac ^ swA) & 3) * 4) * 4;

    // ---- B cp.async: thread -> k row kb (0..15), col groups bc, bc+32
    const int kb = tid >> 5;
    const int bc = tid & 31;
    const int sB = (2 * kb) & 7;
    const float* Bsrc = Bm + (size_t)kb * N + bn + 4 * bc;
    unsigned bdst[2];
#pragma unroll
    for (int u = 0; u < 2; u++)
        bdst[u] = sbase + (unsigned)(2048 + kb * 256 + (((bc + 32 * u) ^ sB) & 63) * 4) * 4;

#define GEMM_ISSUE(it, stg) do {                                               \
        unsigned off_ = (unsigned)(stg) * 24576u;                              \
        CPA16(adst + off_, Asrc + (size_t)(it) * 16);                          \
        const float* bs_ = Bsrc + (size_t)(it) * 16 * N;                       \
        CPA16(bdst[0] + off_, bs_);                                            \
        CPA16(bdst[1] + off_, bs_ + 128);                                      \
    } while (0)

    float acc[4][4][4];
#pragma unroll
    for (int m = 0; m < 4; m++)
#pragma unroll
        for (int nf = 0; nf < 4; nf++)
#pragma unroll
            for (int e = 0; e < 4; e++) acc[m][nf][e] = 0.f;

    GEMM_ISSUE(0, 0); CP_COMMIT();
    GEMM_ISSUE(1, 1); CP_COMMIT();
    GEMM_ISSUE(2, 2); CP_COMMIT();

    const int NIT = K >> 4;
    const int swa = (g >> 1) & 3;

    for (int it = 0; it < NIT; ++it) {
        asm volatile("cp.async.wait_group 2;");
        __syncthreads();
        if (it + 3 < NIT) GEMM_ISSUE(it + 3, (it + 3) & 3);
        CP_COMMIT();

        const unsigned* Sa = S + (it & 3) * 6144;
        const unsigned* Sb = Sa + 2048;

#pragma unroll
        for (int sl = 0; sl < 2; ++sl) {
            uint4 af[4];
            const int cx = ((2 * sl) ^ swa) << 2;
            const int cz = ((2 * sl + 1) ^ swa) << 2;
#pragma unroll
            for (int m = 0; m < 4; m++) {
                int rb = (wm * 64 + m * 16 + g) * 16 + t;
                af[m].x = Sa[rb + cx];
                af[m].y = Sa[rb + 128 + cx];
                af[m].z = Sa[rb + cz];
                af[m].w = Sa[rb + 128 + cz];
            }
            uint2 bf[4];
            const int r0 = (sl * 8 + t) * 256 + (g & 3);
            const int r1 = r0 + 4 * 256;
#pragma unroll
            for (int nf = 0; nf < 4; nf++) {
                int c2 = ((wn * 8 + nf * 2 + (g >> 2)) ^ (2 * t)) & 63;
                bf[nf].x = Sb[r0 + c2 * 4];
                bf[nf].y = Sb[r1 + c2 * 4];
            }
#pragma unroll
            for (int m = 0; m < 4; m++)
#pragma unroll
                for (int nf = 0; nf < 4; nf++)
                    MMA_TF32(acc[m][nf], af[m], bf[nf]);
        }
    }

    // ---- epilogue
#pragma unroll
    for (int m = 0; m < 4; m++) {
        int row = bm + wm * 64 + m * 16 + g;
#pragma unroll
        for (int nf = 0; nf < 4; nf++) {
            int col = bn + wn * 32 + nf * 8 + 2 * t;
            float b0 = bias[col], b1 = bias[col + 1];
            float2 v0 = make_float2(acc[m][nf][0] + b0, acc[m][nf][1] + b1);
            float2 v1 = make_float2(acc[m][nf][2] + b0, acc[m][nf][3] + b1);
            if (roundC) {
                v0.x = __uint_as_float(f2tf32(v0.x));
                v0.y = __uint_as_float(f2tf32(v0.y));
                v1.x = __uint_as_float(f2tf32(v1.x));
                v1.y = __uint_as_float(f2tf32(v1.y));
            }
            *(float2*)&C[(size_t)row * N + col]       = v0;
            *(float2*)&C[(size_t)(row + 8) * N + col] = v1;
        }
    }
#undef GEMM_ISSUE
}

// ---------------- attention v3 (R9, known-good): cp.async KV, Q in regs ------
__global__ __launch_bounds__(256)
void attn_mma_kernel(const int* __restrict__ mask)
{
    extern __shared__ unsigned sm_u[];
    unsigned* pf = sm_u;

    const int tid  = threadIdx.x;
    const int lane = tid & 31;
    const int wq   = tid >> 5;
    const int g    = lane >> 2;
    const int t    = lane & 3;
    const int b    = blockIdx.y >> 4;
    const int h    = blockIdx.y & 15;
    const int q0   = blockIdx.x * 128;

    unsigned sbase;
    asm("{ .reg .u64 x0; cvta.to.shared.u64 x0, %1; cvt.u32.u64 %0, x0; }"
        : "=r"(sbase) : "l"(sm_u));

    uint4 qreg[8];
    {
        const float* qb = g_qkv + ((size_t)(b * SS + q0 + wq * 16)) * QKVN + h * DHH;
#pragma unroll
        for (int sl = 0; sl < 8; sl++) {
            float x0 = qb[(size_t)g * QKVN + sl * 8 + t];
            float x1 = qb[(size_t)(g + 8) * QKVN + sl * 8 + t];
            float x2 = qb[(size_t)g * QKVN + sl * 8 + t + 4];
            float x3 = qb[(size_t)(g + 8) * QKVN + sl * 8 + t + 4];
            qreg[sl].x = __float_as_uint(x0 * 0.03125f);
            qreg[sl].y = __float_as_uint(x1 * 0.03125f);
            qreg[sl].z = __float_as_uint(x2 * 0.03125f);
            qreg[sl].w = __float_as_uint(x3 * 0.03125f);
        }
    }

    const int krow = tid >> 2;
    const int kq   = tid & 3;
    const size_t srcrow = ((size_t)(b * SS) + krow) * QKVN + h * DHH + kq * 4;
    const unsigned kdst = sbase + (unsigned)(8192 + krow * 68 + kq * 4) * 4;
    const unsigned vdst = sbase + (unsigned)(16896 + krow * 68 + kq * 4) * 4;

#define AT_ISSUE(ch) do {                                                      \
        unsigned bo_ = ((ch) & 1) ? 17408u : 0u;                               \
        const float* kp_ = g_qkv + srcrow + (size_t)(ch) * 64 * QKVN + 1024;   \
        const float* vp_ = kp_ + 1024;                                         \
        CPA16(kdst + bo_,       kp_);                                          \
        CPA16(kdst + bo_ + 64,  kp_ + 16);                                     \
        CPA16(kdst + bo_ + 128, kp_ + 32);                                     \
        CPA16(kdst + bo_ + 192, kp_ + 48);                                     \
        CPA16(vdst + bo_,       vp_);                                          \
        CPA16(vdst + bo_ + 64,  vp_ + 16);                                     \
        CPA16(vdst + bo_ + 128, vp_ + 32);                                     \
        CPA16(vdst + bo_ + 192, vp_ + 48);                                     \
        CP_COMMIT();                                                           \
    } while (0)

    float o[8][4];
#pragma unroll
    for (int nf = 0; nf < 8; nf++)
#pragma unroll
        for (int e = 0; e < 4; e++) o[nf][e] = 0.f;
    float m0 = -1e30f, m1 = -1e30f, l0 = 0.f, l1 = 0.f;

    const size_t mbase = (size_t)b * SS * SS;
    unsigned* pw = pf + wq * 1024;

    AT_ISSUE(0);

#pragma unroll 1
    for (int ch = 0; ch < 16; ++ch) {
        if (ch + 1 < 16) {
            AT_ISSUE(ch + 1);
            asm volatile("cp.async.wait_group 1;");
        } else {
            asm volatile("cp.async.wait_group 0;");
        }
        __syncthreads();

        const unsigned* KS = sm_u + 8192  + ((ch & 1) ? 4352 : 0);
        const unsigned* VS = sm_u + 16896 + ((ch & 1) ? 4352 : 0);

        float s[8][4];
#pragma unroll
        for (int nf = 0; nf < 8; nf++)
#pragma unroll
            for (int e = 0; e < 4; e++) s[nf][e] = 0.f;
#pragma unroll
        for (int sl = 0; sl < 8; ++sl) {
            const int ab = g * 68 + sl * 8 + t;
#pragma unroll
            for (int nf = 0; nf < 8; nf++) {
                uint2 bb;
                bb.x = KS[nf * 544 + ab];
                bb.y = KS[nf * 544 + ab + 4];
                MMA_TF32(s[nf], qreg[sl], bb);
            }
        }

        const int rg = q0 + wq * 16 + g;
        const int kb = ch * 64;
#pragma unroll
        for (int nf = 0; nf < 8; nf++) {
            int col = kb + nf * 8 + 2 * t;
            int2 mk0 = *(const int2*)(mask + mbase + (size_t)rg * SS + col);
            int2 mk1 = *(const int2*)(mask + mbase + (size_t)(rg + 8) * SS + col);
            if (mk0.x) s[nf][0] = -1e9f;
            if (mk0.y) s[nf][1] = -1e9f;
            if (mk1.x) s[nf][2] = -1e9f;
            if (mk1.y) s[nf][3] = -1e9f;
        }

        float mx0 = -1e30f, mx1 = -1e30f;
#pragma unroll
        for (int nf = 0; nf < 8; nf++) {
            mx0 = fmaxf(mx0, fmaxf(s[nf][0], s[nf][1]));
            mx1 = fmaxf(mx1, fmaxf(s[nf][2], s[nf][3]));
        }
        mx0 = fmaxf(mx0, __shfl_xor_sync(0xffffffffu, mx0, 1));
        mx0 = fmaxf(mx0, __shfl_xor_sync(0xffffffffu, mx0, 2));
        mx1 = fmaxf(mx1, __shfl_xor_sync(0xffffffffu, mx1, 1));
        mx1 = fmaxf(mx1, __shfl_xor_sync(0xffffffffu, mx1, 2));
        float mn0 = fmaxf(m0, mx0), mn1 = fmaxf(m1, mx1);
        float a0 = __expf(m0 - mn0), a1 = __expf(m1 - mn1);
        m0 = mn0; m1 = mn1;

        float p[8][4];
        float ps0 = 0.f, ps1 = 0.f;
#pragma unroll
        for (int nf = 0; nf < 8; nf++) {
            p[nf][0] = __expf(s[nf][0] - mn0);
            p[nf][1] = __expf(s[nf][1] - mn0);
            p[nf][2] = __expf(s[nf][2] - mn1);
            p[nf][3] = __expf(s[nf][3] - mn1);
            ps0 += p[nf][0] + p[nf][1];
            ps1 += p[nf][2] + p[nf][3];
        }
        ps0 += __shfl_xor_sync(0xffffffffu, ps0, 1);
        ps0 += __shfl_xor_sync(0xffffffffu, ps0, 2);
        ps1 += __shfl_xor_sync(0xffffffffu, ps1, 1);
        ps1 += __shfl_xor_sync(0xffffffffu, ps1, 2);
        l0 = l0 * a0 + ps0;
        l1 = l1 * a1 + ps1;
#pragma unroll
        for (int nf = 0; nf < 8; nf++) {
            o[nf][0] *= a0; o[nf][1] *= a0;
            o[nf][2] *= a1; o[nf][3] *= a1;
        }

        {
            int ln0 = (g << 2) | ((2 * t) & 3);
            int ln1 = (g << 2) | ((2 * t + 1) & 3);
            int sl  = (t >> 1) << 1;
#pragma unroll
            for (int nf = 0; nf < 8; nf++) {
                uint2 w0 = make_uint2(f2tf32(p[nf][0]), f2tf32(p[nf][2]));
                uint2 w1 = make_uint2(f2tf32(p[nf][1]), f2tf32(p[nf][3]));
                *(uint2*)&pw[nf * 128 + ln0 * 4 + sl] = w0;
                *(uint2*)&pw[nf * 128 + ln1 * 4 + sl] = w1;
            }
        }
        __syncwarp();

#pragma unroll
        for (int sl = 0; sl < 8; ++sl) {
            uint4 a = *(const uint4*)&pw[sl * 128 + lane * 4];
            const int vb = (sl * 8 + t) * 68 + g;
#pragma unroll
            for (int nf = 0; nf < 8; nf++) {
                uint2 bb;
                bb.x = VS[vb + nf * 8];
                bb.y = VS[vb + nf * 8 + 4 * 68];
                MMA_TF32(o[nf], a, bb);
            }
        }
        __syncthreads();
    }

    float i0 = 1.f / l0, i1 = 1.f / l1;
    int row0 = q0 + wq * 16 + g;
#pragma unroll
    for (int nf = 0; nf < 8; nf++) {
        int col = h * DHH + nf * 8 + 2 * t;
        float2 v0 = make_float2(__uint_as_float(f2tf32(o[nf][0] * i0)),
                                __uint_as_float(f2tf32(o[nf][1] * i0)));
        float2 v1 = make_float2(__uint_as_float(f2tf32(o[nf][2] * i1)),
                                __uint_as_float(f2tf32(o[nf][3] * i1)));
        *(float2*)(g_ctx + (size_t)(b * SS + row0) * DD + col)     = v0;
        *(float2*)(g_ctx + (size_t)(b * SS + row0 + 8) * DD + col) = v1;
    }
#undef AT_ISSUE
}

// ---------------- launch -----------------------------------------------------
extern "C" void kernel_launch(void* const* d_in, const int* in_sizes, int n_in,
                              void* d_out, int out_size)
{
    const float* x  = (const float*)d_in[0];
    const int* mask = (const int*)d_in[1];
    const float* Wq = (const float*)d_in[2];
    const float* bq = (const float*)d_in[3];
    const float* Wk = (const float*)d_in[4];
    const float* bk = (const float*)d_in[5];
    const float* Wv = (const float*)d_in[6];
    const float* bv = (const float*)d_in[7];
    const float* Wo = (const float*)d_in[8];
    const float* bo = (const float*)d_in[9];
    float* out = (float*)d_out;

    void *p_w, *p_b, *p_qkv, *p_ctx, *p_xt, *p_wo;
    cudaGetSymbolAddress(&p_w, g_w);
    cudaGetSymbolAddress(&p_b, g_b);
    cudaGetSymbolAddress(&p_qkv, g_qkv);
    cudaGetSymbolAddress(&p_ctx, g_ctx);
    cudaGetSymbolAddress(&p_xt, g_xt);
    cudaGetSymbolAddress(&p_wo, g_wo);

    const int ATTN_SMEM = 25600 * (int)sizeof(unsigned);     // 100KB
    const int GEMM_SMEM = 4 * 6144 * (int)sizeof(unsigned);  // 96KB
    static int smem_set = 0;
    if (!smem_set) {
        cudaFuncSetAttribute(attn_mma_kernel, cudaFuncAttributeMaxDynamicSharedMemorySize, ATTN_SMEM);
        cudaFuncSetAttribute(tf32_gemm_bias, cudaFuncAttributeMaxDynamicSharedMemorySize, GEMM_SMEM);
        smem_set = 1;
    }

    round_tf32_kernel<<<(MROWS * KDIM / 4 + 255) / 256, 256>>>(
        (const float4*)x, (float4*)p_xt, MROWS * KDIM / 4);
    round_tf32_kernel<<<(KDIM * DD / 4 + 255) / 256, 256>>>(
        (const float4*)Wo, (float4*)p_wo, KDIM * DD / 4);
    pack_w_kernel<<<(KDIM * QKVN + 255) / 256, 256>>>(Wq, bq, Wk, bk, Wv, bv);

    // QKV projection -> tf32-rounded
    tf32_gemm_bias<<<dim3(QKVN / 256, MROWS / 128), 512, GEMM_SMEM>>>(
        (const float*)p_xt, (const float*)p_w, (const float*)p_b, (float*)p_qkv,
        MROWS, QKVN, KDIM, 1);

    // fused masked attention
    attn_mma_kernel<<<dim3(SS / 128, BB * HH), 256, ATTN_SMEM>>>(mask);

    // output projection -> fp32 output
    tf32_gemm_bias<<<dim3(DD / 256, MROWS / 128), 512, GEMM_SMEM>>>(
        (const float*)p_ctx, (const float*)p_wo, bo, out, MROWS, DD, KDIM, 0);
}

// round 15
// speedup vs baseline: 2.2153x; 1.9557x over previous
#include <cuda_runtime.h>
#include <cuda_fp16.h>
#include <cstdint>

#define BB 8
#define SS 1024
#define DD 1024
#define HH 16
#define DHH 64
#define QKVN 3072
#define MROWS 8192
#define KDIM 1024

// ---------------- scratch ----------------------------------------------------
__device__ __half   g_xh[(size_t)MROWS * KDIM];          // inputs fp16
__device__ unsigned g_wph[(size_t)(KDIM / 2) * QKVN];    // QKV weights, k-pair half2
__device__ float    g_b[QKVN];
__device__ __half   g_qkvh[(size_t)MROWS * QKVN];        // QKV fp16
__device__ __half   g_ctxh[(size_t)MROWS * DD];          // attn out fp16
__device__ unsigned g_woph[(size_t)(KDIM / 2) * DD];     // Wo, k-pair half2

// ---------------- helpers ----------------------------------------------------
__device__ __forceinline__ unsigned h2u(__half2 v) { return *reinterpret_cast<unsigned*>(&v); }

#define MMA_F16(c, a, b)                                                      \
    asm volatile("mma.sync.aligned.m16n8k16.row.col.f32.f16.f16.f32 "         \
                 "{%0,%1,%2,%3}, {%4,%5,%6,%7}, {%8,%9}, {%0,%1,%2,%3};"      \
                 : "+f"((c)[0]), "+f"((c)[1]), "+f"((c)[2]), "+f"((c)[3])     \
                 : "r"((a).x), "r"((a).y), "r"((a).z), "r"((a).w),            \
                   "r"((b).x), "r"((b).y))

#define LDSM_X4_T(r0, r1, r2, r3, addr)                                       \
    asm volatile("ldmatrix.sync.aligned.m8n8.x4.trans.shared.b16 "            \
                 "{%0,%1,%2,%3}, [%4];"                                       \
                 : "=r"(r0), "=r"(r1), "=r"(r2), "=r"(r3) : "r"(addr))

#define CPA16(dst, src)                                                       \
    asm volatile("cp.async.cg.shared.global [%0], [%1], 16;"                  \
                 :: "r"(dst), "l"(__cvta_generic_to_global(src)))
#define CP_COMMIT() asm volatile("cp.async.commit_group;")

__device__ __forceinline__ uint32_t smem_u32(const void* p) {
    uint32_t a;
    asm("{ .reg .u64 x0; cvta.to.shared.u64 x0, %1; cvt.u32.u64 %0, x0; }"
        : "=r"(a) : "l"(p));
    return a;
}

// ---------------- aux kernels ------------------------------------------------
__global__ void cvt_f2h_kernel(const float4* __restrict__ in, __half2* __restrict__ out, int n4)
{
    int i = blockIdx.x * 256 + threadIdx.x;
    if (i < n4) {
        float4 v = in[i];
        out[2 * i]     = __floats2half2_rn(v.x, v.y);
        out[2 * i + 1] = __floats2half2_rn(v.z, v.w);
    }
}

// pack Wq/Wk/Wv [H,D,DH] -> g_wph [K/2][3072] half2 over k-pairs; bias fp32
__global__ void pack_w_h_kernel(const float* __restrict__ Wq, const float* __restrict__ bq,
                                const float* __restrict__ Wk, const float* __restrict__ bk,
                                const float* __restrict__ Wv, const float* __restrict__ bv)
{
    int idx = blockIdx.x * 256 + threadIdx.x;
    if (idx < (KDIM / 2) * QKVN) {
        int kk  = idx / QKVN;
        int col = idx - kk * QKVN;
        int which = col >> 10;
        int he  = col & 1023;
        int h   = he >> 6;
        int e   = he & 63;
        const float* W = (which == 0) ? Wq : ((which == 1) ? Wk : Wv);
        float w0 = W[(h * KDIM + 2 * kk) * DHH + e];
        float w1 = W[(h * KDIM + 2 * kk + 1) * DHH + e];
        ((__half2*)g_wph)[idx] = __floats2half2_rn(w0, w1);
    }
    if (idx < QKVN) {
        int which = idx >> 10;
        int he = idx & 1023;
        const float* bb = (which == 0) ? bq : ((which == 1) ? bk : bv);
        g_b[idx] = bb[he];
    }
}

// pack Wo [K][N] -> g_woph [K/2][N] half2 over k-pairs
__global__ void pack_wo_h_kernel(const float* __restrict__ Wo)
{
    int idx = blockIdx.x * 256 + threadIdx.x;
    if (idx < (KDIM / 2) * DD) {
        int kk = idx >> 10;
        int n  = idx & 1023;
        ((__half2*)g_woph)[idx] = __floats2half2_rn(Wo[(size_t)(2 * kk) * DD + n],
                                                    Wo[(size_t)(2 * kk + 1) * DD + n]);
    }
}

// ---------------- fp16 GEMM: 128x256 tile, BK=32, 4-stage cp.async -----------
// A smem [128 rows][32 k] fp16 (64B/row, chunk swizzle c^((row>>1)&3)).
// B smem [16 kk][256 n] u32 half2-packed, v4 XOR group swizzle.
// Stage = 2048 + 4096 = 6144 words (24KB); 4 stages = 96KB.
__global__ __launch_bounds__(256, 1)
void h16_gemm_bias(const __half* __restrict__ A, const unsigned* __restrict__ Bp,
                   const float* __restrict__ bias, void* __restrict__ Cout,
                   int M, int N, int K, int outHalf)
{
    extern __shared__ unsigned S[];

    const int tid  = threadIdx.x;
    const int lane = tid & 31;
    const int wid  = tid >> 5;
    const int wm   = wid >> 2;          // 0..1
    const int wn   = wid & 3;           // 0..3
    const int bm   = blockIdx.y * 128;
    const int bn   = blockIdx.x * 256;
    const int g    = lane >> 2;
    const int t    = lane & 3;

    const unsigned sbase = smem_u32(S);

    // A cp.async: thread -> row tid>>1, chunks (tid&1)*2 + {0,1}
    const int arow = tid >> 1;
    const int ac0  = (tid & 1) * 2;
    const int aswz = (arow >> 1) & 3;
    const __half* Asrc = A + (size_t)(bm + arow) * K;
    const unsigned adst0 = sbase + (unsigned)(arow * 16 + ((ac0 ^ aswz) & 3) * 4) * 4;
    const unsigned adst1 = sbase + (unsigned)(arow * 16 + (((ac0 + 1) ^ aswz) & 3) * 4) * 4;

    // B cp.async: thread -> kk row tid>>4, 4 col groups (tid&15)+16u
    const int kb = tid >> 4;
    const int bc = tid & 15;
    const int sB = (2 * kb) & 7;
    const unsigned* Bsrc = Bp + (size_t)kb * N + bn + 4 * bc;
    unsigned bdst[4];
#pragma unroll
    for (int u = 0; u < 4; u++)
        bdst[u] = sbase + (unsigned)(2048 + kb * 256 + (((bc + 16 * u) ^ sB) & 63) * 4) * 4;

#define GEMM_ISSUE(it, stg) do {                                               \
        unsigned off_ = (unsigned)(stg) * 24576u;                              \
        const __half* as_ = Asrc + (size_t)(it) * 32 + ac0 * 8;                \
        CPA16(adst0 + off_, as_);                                              \
        CPA16(adst1 + off_, as_ + 8);                                          \
        const unsigned* bs_ = Bsrc + (size_t)(it) * 16 * N;                    \
        CPA16(bdst[0] + off_, bs_);                                            \
        CPA16(bdst[1] + off_, bs_ + 64);                                       \
        CPA16(bdst[2] + off_, bs_ + 128);                                      \
        CPA16(bdst[3] + off_, bs_ + 192);                                      \
    } while (0)

    float acc[4][8][4];
#pragma unroll
    for (int m = 0; m < 4; m++)
#pragma unroll
        for (int nf = 0; nf < 8; nf++)
#pragma unroll
            for (int e = 0; e < 4; e++) acc[m][nf][e] = 0.f;

    GEMM_ISSUE(0, 0); CP_COMMIT();
    GEMM_ISSUE(1, 1); CP_COMMIT();
    GEMM_ISSUE(2, 2); CP_COMMIT();

    const int NIT = K >> 5;              // BK=32
    const int aswzL = (g >> 1) & 3;      // frag-load swizzle (row-invariant)

    for (int it = 0; it < NIT; ++it) {
        asm volatile("cp.async.wait_group 2;");
        __syncthreads();
        if (it + 3 < NIT) GEMM_ISSUE(it + 3, (it + 3) & 3);
        CP_COMMIT();

        const unsigned* Sa = S + (it & 3) * 6144;
        const unsigned* Sb = Sa + 2048;

#pragma unroll
        for (int sl = 0; sl < 2; ++sl) {
            uint4 af[4];
            const int cA0 = ((2 * sl) ^ aswzL) * 4;
            const int cA1 = ((2 * sl + 1) ^ aswzL) * 4;
#pragma unroll
            for (int m = 0; m < 4; m++) {
                int r0w = (wm * 64 + m * 16 + g) * 16;
                int r1w = r0w + 128;
                af[m].x = Sa[r0w + cA0 + t];
                af[m].y = Sa[r1w + cA0 + t];
                af[m].z = Sa[r0w + cA1 + t];
                af[m].w = Sa[r1w + cA1 + t];
            }
            uint2 bf[8];
            const int r0 = (sl * 8 + t) * 256 + (g & 3);
            const int r1 = r0 + 4 * 256;
#pragma unroll
            for (int nf = 0; nf < 8; nf++) {
                int c2 = ((wn * 16 + nf * 2 + (g >> 2)) ^ (2 * t)) & 63;
                bf[nf].x = Sb[r0 + c2 * 4];
                bf[nf].y = Sb[r1 + c2 * 4];
            }
#pragma unroll
            for (int m = 0; m < 4; m++)
#pragma unroll
                for (int nf = 0; nf < 8; nf++)
                    MMA_F16(acc[m][nf], af[m], bf[nf]);
        }
    }

    // ---- epilogue
#pragma unroll
    for (int m = 0; m < 4; m++) {
        int row = bm + wm * 64 + m * 16 + g;
#pragma unroll
        for (int nf = 0; nf < 8; nf++) {
            int col = bn + wn * 64 + nf * 8 + 2 * t;
            float b0 = bias[col], b1 = bias[col + 1];
            float v00 = acc[m][nf][0] + b0, v01 = acc[m][nf][1] + b1;
            float v10 = acc[m][nf][2] + b0, v11 = acc[m][nf][3] + b1;
            if (outHalf) {
                __half* C = (__half*)Cout;
                *(__half2*)(C + (size_t)row * N + col)       = __floats2half2_rn(v00, v01);
                *(__half2*)(C + (size_t)(row + 8) * N + col) = __floats2half2_rn(v10, v11);
            } else {
                float* C = (float*)Cout;
                *(float2*)(C + (size_t)row * N + col)       = make_float2(v00, v01);
                *(float2*)(C + (size_t)(row + 8) * N + col) = make_float2(v10, v11);
            }
        }
    }
#undef GEMM_ISSUE
}

// ---------------- fp16 flash attention ---------------------------------------
// grid (S/128, B*H), 256 threads, occ 2. Smem (words):
//   K: [buf][64 rows][36]  at 0      (2 x 2304)
//   V: [buf][64 rows][36]  at 4608   (2 x 2304)    total 9216 words = 36864B
__global__ __launch_bounds__(256, 2)
void attn_h_kernel(const int* __restrict__ mask)
{
    extern __shared__ unsigned sm_u[];

    const int tid  = threadIdx.x;
    const int lane = tid & 31;
    const int wq   = tid >> 5;
    const int g    = lane >> 2;
    const int t    = lane & 3;
    const int b    = blockIdx.y >> 4;
    const int h    = blockIdx.y & 15;
    const int q0   = blockIdx.x * 128;

    const unsigned sbase = smem_u32(sm_u);

    // ---- Q a-frags in registers (fp16, scale 1/32 exact)
    uint4 qreg[4];
    {
        const __half* qb = g_qkvh + (size_t)(b * SS + q0 + wq * 16) * QKVN + h * DHH;
        const __half2 sc = __floats2half2_rn(0.03125f, 0.03125f);
#pragma unroll
        for (int sl = 0; sl < 4; sl++) {
            __half2 h0 = *(const __half2*)(qb + (size_t)g * QKVN + sl * 16 + 2 * t);
            __half2 h1 = *(const __half2*)(qb + (size_t)(g + 8) * QKVN + sl * 16 + 2 * t);
            __half2 h2 = *(const __half2*)(qb + (size_t)g * QKVN + sl * 16 + 8 + 2 * t);
            __half2 h3 = *(const __half2*)(qb + (size_t)(g + 8) * QKVN + sl * 16 + 8 + 2 * t);
            __half2 m0h = __hmul2(h0, sc), m1h = __hmul2(h1, sc);
            __half2 m2h = __hmul2(h2, sc), m3h = __hmul2(h3, sc);
            qreg[sl].x = h2u(m0h);
            qreg[sl].y = h2u(m1h);
            qreg[sl].z = h2u(m2h);
            qreg[sl].w = h2u(m3h);
        }
    }

    // ---- cp.async mapping: thread -> KV row tid>>2, chunks (tid&3)*2 + {0,1}
    const int krow = tid >> 2;
    const int kc0  = (tid & 3) * 2;
    const size_t srcbyte = (((size_t)(b * SS) + krow) * QKVN + 1024 + h * DHH) * 2 + kc0 * 16;
    const unsigned kdst = sbase + (unsigned)(krow * 144 + kc0 * 16);
    const unsigned vdst = sbase + 18432u + (unsigned)(krow * 144 + kc0 * 16);   // 4608 words

#define AT_ISSUE(ch) do {                                                      \
        unsigned bo_ = ((ch) & 1) ? 9216u : 0u;    /* 2304 words */            \
        const char* kp_ = (const char*)g_qkvh + srcbyte + (size_t)(ch) * 64 * QKVN * 2; \
        const char* vp_ = kp_ + 2048;                                          \
        CPA16(kdst + bo_,      kp_);                                           \
        CPA16(kdst + bo_ + 16, kp_ + 16);                                      \
        CPA16(vdst + bo_,      vp_);                                           \
        CPA16(vdst + bo_ + 16, vp_ + 16);                                      \
        CP_COMMIT();                                                           \
    } while (0)

    float o[8][4];
#pragma unroll
    for (int nf = 0; nf < 8; nf++)
#pragma unroll
        for (int e = 0; e < 4; e++) o[nf][e] = 0.f;
    float m0 = -1e30f, m1 = -1e30f, l0 = 0.f, l1 = 0.f;

    const size_t mbase = (size_t)b * SS * SS;

    AT_ISSUE(0);

#pragma unroll 1
    for (int ch = 0; ch < 16; ++ch) {
        if (ch + 1 < 16) {
            AT_ISSUE(ch + 1);
            asm volatile("cp.async.wait_group 1;");
        } else {
            asm volatile("cp.async.wait_group 0;");
        }
        __syncthreads();

        const unsigned* KS = sm_u + ((ch & 1) ? 2304 : 0);
        const unsigned vbyte = sbase + 18432u + (((ch & 1) ? 9216u : 0u));

        // ---- GEMM1: S[16 q][64 keys] (Q regs x K smem)
        float s[8][4];
#pragma unroll
        for (int nf = 0; nf < 8; nf++)
#pragma unroll
            for (int e = 0; e < 4; e++) s[nf][e] = 0.f;
#pragma unroll
        for (int sl = 0; sl < 4; ++sl) {
#pragma unroll
            for (int nf = 0; nf < 8; nf++) {
                const int ab = (nf * 8 + g) * 36 + sl * 8 + t;
                uint2 bb;
                bb.x = KS[ab];
                bb.y = KS[ab + 4];
                MMA_F16(s[nf], qreg[sl], bb);
            }
        }

        // ---- mask (nonzero -> -1e9)
        const int rg = q0 + wq * 16 + g;
        const int kb = ch * 64;
#pragma unroll
        for (int nf = 0; nf < 8; nf++) {
            int col = kb + nf * 8 + 2 * t;
            int2 mk0 = *(const int2*)(mask + mbase + (size_t)rg * SS + col);
            int2 mk1 = *(const int2*)(mask + mbase + (size_t)(rg + 8) * SS + col);
            if (mk0.x) s[nf][0] = -1e9f;
            if (mk0.y) s[nf][1] = -1e9f;
            if (mk1.x) s[nf][2] = -1e9f;
            if (mk1.y) s[nf][3] = -1e9f;
        }

        // ---- online softmax (fp32)
        float mx0 = -1e30f, mx1 = -1e30f;
#pragma unroll
        for (int nf = 0; nf < 8; nf++) {
            mx0 = fmaxf(mx0, fmaxf(s[nf][0], s[nf][1]));
            mx1 = fmaxf(mx1, fmaxf(s[nf][2], s[nf][3]));
        }
        mx0 = fmaxf(mx0, __shfl_xor_sync(0xffffffffu, mx0, 1));
        mx0 = fmaxf(mx0, __shfl_xor_sync(0xffffffffu, mx0, 2));
        mx1 = fmaxf(mx1, __shfl_xor_sync(0xffffffffu, mx1, 1));
        mx1 = fmaxf(mx1, __shfl_xor_sync(0xffffffffu, mx1, 2));
        float mn0 = fmaxf(m0, mx0), mn1 = fmaxf(m1, mx1);
        float a0 = __expf(m0 - mn0), a1 = __expf(m1 - mn1);
        m0 = mn0; m1 = mn1;

        float ps0 = 0.f, ps1 = 0.f;
#pragma unroll
        for (int nf = 0; nf < 8; nf++) {
            s[nf][0] = __expf(s[nf][0] - mn0);
            s[nf][1] = __expf(s[nf][1] - mn0);
            s[nf][2] = __expf(s[nf][2] - mn1);
            s[nf][3] = __expf(s[nf][3] - mn1);
            ps0 += s[nf][0] + s[nf][1];
            ps1 += s[nf][2] + s[nf][3];
        }
        ps0 += __shfl_xor_sync(0xffffffffu, ps0, 1);
        ps0 += __shfl_xor_sync(0xffffffffu, ps0, 2);
        ps1 += __shfl_xor_sync(0xffffffffu, ps1, 1);
        ps1 += __shfl_xor_sync(0xffffffffu, ps1, 2);
        l0 = l0 * a0 + ps0;
        l1 = l1 * a1 + ps1;
#pragma unroll
        for (int nf = 0; nf < 8; nf++) {
            o[nf][0] *= a0; o[nf][1] *= a0;
            o[nf][2] *= a1; o[nf][3] *= a1;
        }

        // ---- GEMM2: O += P @ V (P frags direct from registers; V via ldmatrix)
#pragma unroll
        for (int sl = 0; sl < 4; ++sl) {
            uint4 a;
            a.x = h2u(__floats2half2_rn(s[2 * sl][0],     s[2 * sl][1]));
            a.y = h2u(__floats2half2_rn(s[2 * sl][2],     s[2 * sl][3]));
            a.z = h2u(__floats2half2_rn(s[2 * sl + 1][0], s[2 * sl + 1][1]));
            a.w = h2u(__floats2half2_rn(s[2 * sl + 1][2], s[2 * sl + 1][3]));
            const unsigned vrow = vbyte + (unsigned)((sl * 16 + (lane & 15)) * 144)
                                        + (unsigned)((lane >> 4) * 16);
#pragma unroll
            for (int nfp = 0; nfp < 4; nfp++) {
                unsigned r0, r1, r2, r3;
                LDSM_X4_T(r0, r1, r2, r3, vrow + nfp * 32);
                uint2 b01 = make_uint2(r0, r1);
                uint2 b23 = make_uint2(r2, r3);
                MMA_F16(o[2 * nfp],     a, b01);
                MMA_F16(o[2 * nfp + 1], a, b23);
            }
        }
        __syncthreads();
    }

    // ---- epilogue -> fp16 ctx
    float i0 = 1.f / l0, i1 = 1.f / l1;
    int row0 = q0 + wq * 16 + g;
    __half* crow = g_ctxh + (size_t)(b * SS + row0) * DD + h * DHH;
#pragma unroll
    for (int nf = 0; nf < 8; nf++) {
        int col = nf * 8 + 2 * t;
        *(__half2*)(crow + col)          = __floats2half2_rn(o[nf][0] * i0, o[nf][1] * i0);
        *(__half2*)(crow + 8 * DD + col) = __floats2half2_rn(o[nf][2] * i1, o[nf][3] * i1);
    }
#undef AT_ISSUE
}

// ---------------- launch -----------------------------------------------------
extern "C" void kernel_launch(void* const* d_in, const int* in_sizes, int n_in,
                              void* d_out, int out_size)
{
    const float* x  = (const float*)d_in[0];
    const int* mask = (const int*)d_in[1];
    const float* Wq = (const float*)d_in[2];
    const float* bq = (const float*)d_in[3];
    const float* Wk = (const float*)d_in[4];
    const float* bk = (const float*)d_in[5];
    const float* Wv = (const float*)d_in[6];
    const float* bv = (const float*)d_in[7];
    const float* Wo = (const float*)d_in[8];
    const float* bo = (const float*)d_in[9];
    float* out = (float*)d_out;

    void *p_xh, *p_wph, *p_b, *p_qkvh, *p_ctxh, *p_woph;
    cudaGetSymbolAddress(&p_xh, g_xh);
    cudaGetSymbolAddress(&p_wph, g_wph);
    cudaGetSymbolAddress(&p_b, g_b);
    cudaGetSymbolAddress(&p_qkvh, g_qkvh);
    cudaGetSymbolAddress(&p_ctxh, g_ctxh);
    cudaGetSymbolAddress(&p_woph, g_woph);

    const int GEMM_SMEM = 4 * 6144 * (int)sizeof(unsigned);  // 96KB
    const int ATTN_SMEM = 9216 * (int)sizeof(unsigned);      // 36864B
    static int smem_set = 0;
    if (!smem_set) {
        cudaFuncSetAttribute(h16_gemm_bias, cudaFuncAttributeMaxDynamicSharedMemorySize, GEMM_SMEM);
        cudaFuncSetAttribute(attn_h_kernel, cudaFuncAttributeMaxDynamicSharedMemorySize, ATTN_SMEM);
        smem_set = 1;
    }

    // aux: conversions + packing
    cvt_f2h_kernel<<<(MROWS * KDIM / 4 + 255) / 256, 256>>>(
        (const float4*)x, (__half2*)p_xh, MROWS * KDIM / 4);
    pack_w_h_kernel<<<((KDIM / 2) * QKVN + 255) / 256, 256>>>(Wq, bq, Wk, bk, Wv, bv);
    pack_wo_h_kernel<<<((KDIM / 2) * DD + 255) / 256, 256>>>(Wo);

    // QKV projection (fp16 mma) -> fp16
    h16_gemm_bias<<<dim3(QKVN / 256, MROWS / 128), 256, GEMM_SMEM>>>(
        (const __half*)p_xh, (const unsigned*)p_wph, (const float*)p_b, p_qkvh,
        MROWS, QKVN, KDIM, 1);

    // fused masked attention (fp16 mma) -> fp16 ctx
    attn_h_kernel<<<dim3(SS / 128, BB * HH), 256, ATTN_SMEM>>>(mask);

    // output projection (fp16 mma) -> fp32 out
    h16_gemm_bias<<<dim3(DD / 256, MROWS / 128), 256, GEMM_SMEM>>>(
        (const __half*)p_ctxh, (const unsigned*)p_woph, bo, out,
        MROWS, DD, KDIM, 0);
}